// round 7
// baseline (speedup 1.0000x reference)
#include <cuda_runtime.h>
#include <cstdint>

#define BATCH 4
#define SEQ   1024
#define NXD   1024
#define NHEAD 16
#define HDIM  64
#define GK    1024

// Scratch (allocation-free rule: __device__ globals)
__device__ float g_q[(size_t)BATCH * NHEAD * SEQ * HDIM];   // tf32-rounded, pre-scaled
__device__ float g_a[(size_t)BATCH * SEQ * NXD];            // tf32-rounded
__device__ float g_x[(size_t)BATCH * SEQ * NXD];            // tf32-rounded copy of x
__device__ float g_wT_attn[(size_t)3 * NXD * NXD];          // tf32-rounded [3072,1024]
__device__ float g_wT_proj[(size_t)NXD * NXD];              // tf32-rounded [1024,1024]

__device__ __forceinline__ uint32_t smem_u32(const void* p) {
    uint32_t a;
    asm("{ .reg .u64 t; cvta.to.shared.u64 t, %1; cvt.u32.u64 %0, t; }"
        : "=r"(a) : "l"(p));
    return a;
}
__device__ __forceinline__ uint32_t cvt_tf32(float f) {
    uint32_t r;
    asm("cvt.rna.tf32.f32 %0, %1;" : "=r"(r) : "f"(f));
    return r;
}
__device__ __forceinline__ float rnd_tf32(float f) {
    return __uint_as_float(cvt_tf32(f));
}
__device__ __forceinline__ void cp16(uint32_t dst, const void* src) {
    asm volatile("cp.async.cg.shared.global [%0], [%1], 16;"
                 :: "r"(dst), "l"(src) : "memory");
}
__device__ __forceinline__ void cp_commit() {
    asm volatile("cp.async.commit_group;" ::: "memory");
}
__device__ __forceinline__ void mma_tf32(float* d,
    uint32_t a0, uint32_t a1, uint32_t a2, uint32_t a3,
    uint32_t b0, uint32_t b1)
{
    asm volatile(
        "mma.sync.aligned.m16n8k8.row.col.f32.tf32.tf32.f32 "
        "{%0,%1,%2,%3}, {%4,%5,%6,%7}, {%8,%9}, {%0,%1,%2,%3};"
        : "+f"(d[0]), "+f"(d[1]), "+f"(d[2]), "+f"(d[3])
        : "r"(a0), "r"(a1), "r"(a2), "r"(a3), "r"(b0), "r"(b1));
}

// ---------------------------------------------------------------------------
// elementwise tf32-round copy (x -> g_x)
// ---------------------------------------------------------------------------
__global__ void __launch_bounds__(256) cvt_copy_kernel(
    const float* __restrict__ src, float* __restrict__ dst)
{
    int i = blockIdx.x * 256 + threadIdx.x;
    float4 v = ((const float4*)src)[i];
    v.x = rnd_tf32(v.x); v.y = rnd_tf32(v.y);
    v.z = rnd_tf32(v.z); v.w = rnd_tf32(v.w);
    ((float4*)dst)[i] = v;
}

// ---------------------------------------------------------------------------
// weight transpose + tf32 round: dst[C][R] = rna(src[R][C])
// ---------------------------------------------------------------------------
__global__ void __launch_bounds__(256) transpose_kernel(
    const float* __restrict__ src, float* __restrict__ dst, int R, int C)
{
    __shared__ float tile[32][33];
    int c0 = blockIdx.x * 32, r0 = blockIdx.y * 32;
    int tx = threadIdx.x & 31, ty = threadIdx.x >> 5;
#pragma unroll
    for (int i = 0; i < 32; i += 8)
        tile[ty + i][tx] = src[(size_t)(r0 + ty + i) * C + c0 + tx];
    __syncthreads();
#pragma unroll
    for (int i = 0; i < 32; i += 8)
        dst[(size_t)(c0 + ty + i) * R + r0 + tx] = rnd_tf32(tile[tx][ty + i]);
}

// ---------------------------------------------------------------------------
// tf32 mma.sync GEMM, pre-rounded inputs, 512 threads (16 warps, 4/SMSP).
// Block tile 128x256, BK=32, warp tile 32x64 (warp grid 4x4), 3-stage cp.async.
// C[m][n] = sum_k A[m][k] * BT[n][k] + bias[n]
// ---------------------------------------------------------------------------
#define TLD 36
#define STG (384 * TLD)                 // floats per stage (A 128 + B 256 rows)
#define GEMM_SMEM (3 * STG * 4)         // 165,888 B

__global__ void __launch_bounds__(512, 1) gemm_mma_kernel(
    const float* __restrict__ A, const float* __restrict__ BT,
    const float* __restrict__ bias, float* __restrict__ Cout,
    float* __restrict__ present, int mode)
{
    extern __shared__ float sm[];

    const int t = threadIdx.x;
    const int lane = t & 31, w = t >> 5;
    const int wm = w >> 2, wn = w & 3;          // 4 x 4 warp grid, 32x64 each
    const int qr = lane >> 2, qc = lane & 3;
    const int m0 = blockIdx.y * 128;
    const int n0 = blockIdx.x * 256;

    uint32_t sa_[3], sb_[3];
#pragma unroll
    for (int s = 0; s < 3; s++) {
        sa_[s] = smem_u32(sm + s * STG);
        sb_[s] = sa_[s] + 128 * TLD * 4;
    }

    float acc[2][8][4];
#pragma unroll
    for (int mt = 0; mt < 2; mt++)
#pragma unroll
        for (int nt = 0; nt < 8; nt++)
#pragma unroll
            for (int r = 0; r < 4; r++) acc[mt][nt][r] = 0.f;

    // A: 1024 16B-chunks, B: 2048 chunks; 512 threads
#pragma unroll
    for (int s = 0; s < 2; s++) {
        const int k0 = s * 32;
#pragma unroll
        for (int i = 0; i < 2; i++) {
            int idx = t + i * 512;
            int row = idx >> 3, ch = idx & 7;
            cp16(sa_[s] + ((uint32_t)row * TLD + ch * 4) * 4,
                 A + (size_t)(m0 + row) * GK + k0 + ch * 4);
        }
#pragma unroll
        for (int i = 0; i < 4; i++) {
            int idx = t + i * 512;
            int row = idx >> 3, ch = idx & 7;
            cp16(sb_[s] + ((uint32_t)row * TLD + ch * 4) * 4,
                 BT + (size_t)(n0 + row) * GK + k0 + ch * 4);
        }
        cp_commit();
    }

    for (int kb = 0; kb < 32; kb++) {
        if (kb < 30)
            asm volatile("cp.async.wait_group 1;" ::: "memory");
        else
            asm volatile("cp.async.wait_group 0;" ::: "memory");
        __syncthreads();

        if (kb + 2 < 32) {
            const int s = (kb + 2) % 3;
            const int k0 = (kb + 2) * 32;
#pragma unroll
            for (int i = 0; i < 2; i++) {
                int idx = t + i * 512;
                int row = idx >> 3, ch = idx & 7;
                cp16(sa_[s] + ((uint32_t)row * TLD + ch * 4) * 4,
                     A + (size_t)(m0 + row) * GK + k0 + ch * 4);
            }
#pragma unroll
            for (int i = 0; i < 4; i++) {
                int idx = t + i * 512;
                int row = idx >> 3, ch = idx & 7;
                cp16(sb_[s] + ((uint32_t)row * TLD + ch * 4) * 4,
                     BT + (size_t)(n0 + row) * GK + k0 + ch * 4);
            }
            cp_commit();
        }

        const uint32_t* ab = (const uint32_t*)(sm + (kb % 3) * STG);
        const uint32_t* bb = ab + 128 * TLD;
#pragma unroll
        for (int ks = 0; ks < 4; ks++) {
            const int k = ks * 8;
            uint32_t af[2][4], bf[8][2];
#pragma unroll
            for (int mt = 0; mt < 2; mt++) {
                const uint32_t* ap = ab + (wm * 32 + mt * 16 + qr) * TLD + k + qc;
                af[mt][0] = ap[0];
                af[mt][1] = ap[8 * TLD];
                af[mt][2] = ap[4];
                af[mt][3] = ap[8 * TLD + 4];
            }
#pragma unroll
            for (int nt = 0; nt < 8; nt++) {
                const uint32_t* bp = bb + (wn * 64 + nt * 8 + qr) * TLD + k + qc;
                bf[nt][0] = bp[0];
                bf[nt][1] = bp[4];
            }
#pragma unroll
            for (int mt = 0; mt < 2; mt++)
#pragma unroll
                for (int nt = 0; nt < 8; nt++)
                    mma_tf32(acc[mt][nt], af[mt][0], af[mt][1], af[mt][2], af[mt][3],
                             bf[nt][0], bf[nt][1]);
        }
    }

#pragma unroll
    for (int mt = 0; mt < 2; mt++) {
#pragma unroll
        for (int nt = 0; nt < 8; nt++) {
            int row = m0 + wm * 32 + mt * 16 + qr;
            int col = n0 + wn * 64 + nt * 8 + qc * 2;
            float bv0 = bias[col], bv1 = bias[col + 1];
            float v00 = acc[mt][nt][0] + bv0, v01 = acc[mt][nt][1] + bv1;
            float v10 = acc[mt][nt][2] + bv0, v11 = acc[mt][nt][3] + bv1;
            if (mode == 1) {
                *(float2*)(Cout + (size_t)row * NXD + col) = make_float2(v00, v01);
                *(float2*)(Cout + (size_t)(row + 8) * NXD + col) = make_float2(v10, v11);
            } else {
                int sec = col >> 10;
                int hn = col & 1023;
                int h = hn >> 6, d = hn & 63;
                if (sec == 0) {   // q: fold softmax scale + tf32 pre-round
                    v00 = rnd_tf32(v00 * 0.125f); v01 = rnd_tf32(v01 * 0.125f);
                    v10 = rnd_tf32(v10 * 0.125f); v11 = rnd_tf32(v11 * 0.125f);
                }
                int b0_ = row >> 10, s0_ = row & 1023;
                size_t i0 = (((size_t)b0_ * NHEAD + h) * SEQ + s0_) * HDIM + d;
                int b1_ = (row + 8) >> 10, s1_ = (row + 8) & 1023;
                size_t i1 = (((size_t)b1_ * NHEAD + h) * SEQ + s1_) * HDIM + d;
                float* base = (sec == 0) ? g_q
                            : (sec == 1) ? present
                            : present + (size_t)BATCH * NHEAD * SEQ * HDIM;
                *(float2*)(base + i0) = make_float2(v00, v01);
                *(float2*)(base + i1) = make_float2(v10, v11);
            }
        }
    }
}

// ---------------------------------------------------------------------------
// Attention via tf32 mma.sync (unchanged from R6)
// ---------------------------------------------------------------------------
#define ALD 68
#define ATTN_SMEM (512 * ALD * 4)   // 139,264 B

__global__ void __launch_bounds__(256, 1) attn_mma_kernel(const float* __restrict__ present)
{
    extern __shared__ float sma[];
    float* Qs = sma;                          // [128][ALD] tf32 bits
    float* Ksb = Qs + 128 * ALD;              // 2 x [64][ALD] (kpos, d)
    float* Vsb = Ksb + 2 * 64 * ALD;          // 2 x [64][ALD] (kpos, d)
    uint32_t* Ps = (uint32_t*)(Vsb + 2 * 64 * ALD);  // [128][ALD]

    const int t = threadIdx.x;
    const int lane = t & 31, w = t >> 5;
    const int qr = lane >> 2, qc = lane & 3;
    const int q0 = blockIdx.x * 128;
    const int h = blockIdx.y;
    const int b = blockIdx.z;

    const float* qptr = g_q + ((size_t)b * NHEAD + h) * SEQ * HDIM;
    const float* kptr = present + ((size_t)b * NHEAD + h) * SEQ * HDIM;
    const float* vptr = kptr + (size_t)BATCH * NHEAD * SEQ * HDIM;

    const uint32_t qs_a = smem_u32(Qs);
    const uint32_t ks_a[2] = { smem_u32(Ksb), smem_u32(Ksb + 64 * ALD) };
    const uint32_t vs_a[2] = { smem_u32(Vsb), smem_u32(Vsb + 64 * ALD) };

#pragma unroll
    for (int i = 0; i < 8; i++) {
        int c = t + i * 256;
        int row = c >> 4, ch = c & 15;
        cp16(qs_a + ((uint32_t)row * ALD + ch * 4) * 4,
             qptr + (size_t)(q0 + row) * HDIM + ch * 4);
    }
#pragma unroll
    for (int i = 0; i < 4; i++) {
        int c = t + i * 256;
        int row = c >> 4, ch = c & 15;
        uint32_t off = ((uint32_t)row * ALD + ch * 4) * 4;
        cp16(ks_a[0] + off, kptr + (size_t)row * HDIM + ch * 4);
        cp16(vs_a[0] + off, vptr + (size_t)row * HDIM + ch * 4);
    }
    cp_commit();

    float oacc[8][4];
#pragma unroll
    for (int nt = 0; nt < 8; nt++)
#pragma unroll
        for (int r = 0; r < 4; r++) oacc[nt][r] = 0.f;
    float m0 = -1e30f, m1 = -1e30f, l0 = 0.f, l1 = 0.f;

    const int wrow = w * 16;
    const int qg0 = q0 + wrow + qr;
    const int qg1 = qg0 + 8;
    const int qmax = q0 + wrow + 15;
    const int nj = blockIdx.x * 2 + 2;

    for (int jt = 0; jt < nj; jt++) {
        const int j0 = jt * 64;
        asm volatile("cp.async.wait_group 0;" ::: "memory");
        __syncthreads();

        if (jt + 1 < nj) {
            const int buf = (jt + 1) & 1;
            const int jr = (jt + 1) * 64;
#pragma unroll
            for (int i = 0; i < 4; i++) {
                int c = t + i * 256;
                int row = c >> 4, ch = c & 15;
                uint32_t off = ((uint32_t)row * ALD + ch * 4) * 4;
                cp16(ks_a[buf] + off, kptr + (size_t)(jr + row) * HDIM + ch * 4);
                cp16(vs_a[buf] + off, vptr + (size_t)(jr + row) * HDIM + ch * 4);
            }
            cp_commit();
        }
        if (j0 > qmax) continue;

        const float* Kf = Ksb + (jt & 1) * 64 * ALD;
        const float* Vf = Vsb + (jt & 1) * 64 * ALD;
        const uint32_t* Qu = (const uint32_t*)Qs;

        // ---- S = Q @ K^T ----
        float sacc[8][4];
#pragma unroll
        for (int nt = 0; nt < 8; nt++)
#pragma unroll
            for (int r = 0; r < 4; r++) sacc[nt][r] = 0.f;

#pragma unroll
        for (int ks = 0; ks < 8; ks++) {
            const int k = ks * 8;
            uint32_t a0 = Qu[(wrow + qr) * ALD + k + qc];
            uint32_t a1 = Qu[(wrow + qr + 8) * ALD + k + qc];
            uint32_t a2 = Qu[(wrow + qr) * ALD + k + qc + 4];
            uint32_t a3 = Qu[(wrow + qr + 8) * ALD + k + qc + 4];
#pragma unroll
            for (int nt = 0; nt < 8; nt++) {
                uint32_t b0 = cvt_tf32(Kf[(nt * 8 + qr) * ALD + k + qc]);
                uint32_t b1 = cvt_tf32(Kf[(nt * 8 + qr) * ALD + k + qc + 4]);
                mma_tf32(sacc[nt], a0, a1, a2, a3, b0, b1);
            }
        }

        // ---- causal mask + row max ----
        float rx0 = -1e30f, rx1 = -1e30f;
#pragma unroll
        for (int nt = 0; nt < 8; nt++) {
            int kg = j0 + nt * 8 + qc * 2;
            if (kg > qg0)     sacc[nt][0] = -1e30f;
            if (kg + 1 > qg0) sacc[nt][1] = -1e30f;
            if (kg > qg1)     sacc[nt][2] = -1e30f;
            if (kg + 1 > qg1) sacc[nt][3] = -1e30f;
            rx0 = fmaxf(rx0, fmaxf(sacc[nt][0], sacc[nt][1]));
            rx1 = fmaxf(rx1, fmaxf(sacc[nt][2], sacc[nt][3]));
        }
        rx0 = fmaxf(rx0, __shfl_xor_sync(0xffffffffu, rx0, 1));
        rx0 = fmaxf(rx0, __shfl_xor_sync(0xffffffffu, rx0, 2));
        rx1 = fmaxf(rx1, __shfl_xor_sync(0xffffffffu, rx1, 1));
        rx1 = fmaxf(rx1, __shfl_xor_sync(0xffffffffu, rx1, 2));

        float nm0 = fmaxf(m0, rx0), nm1 = fmaxf(m1, rx1);
        float cr0 = __expf(m0 - nm0), cr1 = __expf(m1 - nm1);

        // ---- exp, row sum, stage P (tf32) ----
        float rs0 = 0.f, rs1 = 0.f;
#pragma unroll
        for (int nt = 0; nt < 8; nt++) {
            float p00 = __expf(sacc[nt][0] - nm0);
            float p01 = __expf(sacc[nt][1] - nm0);
            float p10 = __expf(sacc[nt][2] - nm1);
            float p11 = __expf(sacc[nt][3] - nm1);
            rs0 += p00 + p01;
            rs1 += p10 + p11;
            uint32_t col = nt * 8 + qc * 2;
            *(uint2*)&Ps[(wrow + qr) * ALD + col]     = make_uint2(cvt_tf32(p00), cvt_tf32(p01));
            *(uint2*)&Ps[(wrow + qr + 8) * ALD + col] = make_uint2(cvt_tf32(p10), cvt_tf32(p11));
        }
        rs0 += __shfl_xor_sync(0xffffffffu, rs0, 1);
        rs0 += __shfl_xor_sync(0xffffffffu, rs0, 2);
        rs1 += __shfl_xor_sync(0xffffffffu, rs1, 1);
        rs1 += __shfl_xor_sync(0xffffffffu, rs1, 2);

        l0 = l0 * cr0 + rs0;  m0 = nm0;
        l1 = l1 * cr1 + rs1;  m1 = nm1;
#pragma unroll
        for (int nt = 0; nt < 8; nt++) {
            oacc[nt][0] *= cr0;  oacc[nt][1] *= cr0;
            oacc[nt][2] *= cr1;  oacc[nt][3] *= cr1;
        }
        __syncwarp();

        // ---- O += P @ V ----
#pragma unroll
        for (int ks = 0; ks < 8; ks++) {
            const int k = ks * 8;
            uint32_t a0 = Ps[(wrow + qr) * ALD + k + qc];
            uint32_t a1 = Ps[(wrow + qr + 8) * ALD + k + qc];
            uint32_t a2 = Ps[(wrow + qr) * ALD + k + qc + 4];
            uint32_t a3 = Ps[(wrow + qr + 8) * ALD + k + qc + 4];
#pragma unroll
            for (int nt = 0; nt < 8; nt++) {
                uint32_t b0 = cvt_tf32(Vf[(k + qc) * ALD + nt * 8 + qr]);
                uint32_t b1 = cvt_tf32(Vf[(k + qc + 4) * ALD + nt * 8 + qr]);
                mma_tf32(oacc[nt], a0, a1, a2, a3, b0, b1);
            }
        }
        __syncwarp();
    }

    // ---- epilogue ----
    __syncthreads();
    float* Pf = (float*)Ps;
    float inv0 = 1.f / l0, inv1 = 1.f / l1;
#pragma unroll
    for (int nt = 0; nt < 8; nt++) {
        uint32_t col = nt * 8 + qc * 2;
        *(float2*)&Pf[(wrow + qr) * ALD + col] =
            make_float2(oacc[nt][0] * inv0, oacc[nt][1] * inv0);
        *(float2*)&Pf[(wrow + qr + 8) * ALD + col] =
            make_float2(oacc[nt][2] * inv1, oacc[nt][3] * inv1);
    }
    __syncthreads();
    for (int idx = t; idx < 128 * 16; idx += 256) {
        int row = idx >> 4, ch = idx & 15;
        float4 v = *(float4*)&Pf[row * ALD + ch * 4];
        v.x = rnd_tf32(v.x); v.y = rnd_tf32(v.y);
        v.z = rnd_tf32(v.z); v.w = rnd_tf32(v.w);
        *(float4*)(g_a + ((size_t)b * SEQ + q0 + row) * NXD + h * HDIM + ch * 4) = v;
    }
}

// ---------------------------------------------------------------------------
extern "C" void kernel_launch(void* const* d_in, const int* in_sizes, int n_in,
                              void* d_out, int out_size)
{
    const float* x      = (const float*)d_in[0];
    const float* w_attn = (const float*)d_in[1];
    const float* b_attn = (const float*)d_in[2];
    const float* w_proj = (const float*)d_in[3];
    const float* b_proj = (const float*)d_in[4];

    float* out = (float*)d_out;
    float* present = out + (size_t)BATCH * SEQ * NXD;  // (2,B,NH,S,HD)

    cudaFuncSetAttribute(gemm_mma_kernel,
                         cudaFuncAttributeMaxDynamicSharedMemorySize, GEMM_SMEM);
    cudaFuncSetAttribute(attn_mma_kernel,
                         cudaFuncAttributeMaxDynamicSharedMemorySize, ATTN_SMEM);

    float* wT_attn;  cudaGetSymbolAddress((void**)&wT_attn, g_wT_attn);
    float* wT_proj;  cudaGetSymbolAddress((void**)&wT_proj, g_wT_proj);
    float* a_ptr;    cudaGetSymbolAddress((void**)&a_ptr, g_a);
    float* x_ptr;    cudaGetSymbolAddress((void**)&x_ptr, g_x);

    cvt_copy_kernel<<<(BATCH * SEQ * NXD / 4) / 256, 256>>>(x, x_ptr);
    transpose_kernel<<<dim3(3 * NXD / 32, NXD / 32), 256>>>(w_attn, wT_attn, NXD, 3 * NXD);
    transpose_kernel<<<dim3(NXD / 32, NXD / 32), 256>>>(w_proj, wT_proj, NXD, NXD);

    gemm_mma_kernel<<<dim3(3 * NXD / 256, BATCH * SEQ / 128), 512, GEMM_SMEM>>>(
        x_ptr, wT_attn, b_attn, nullptr, present, 0);

    attn_mma_kernel<<<dim3(SEQ / 128, NHEAD, BATCH), 256, ATTN_SMEM>>>(present);

    gemm_mma_kernel<<<dim3(NXD / 256, BATCH * SEQ / 128), 512, GEMM_SMEM>>>(
        a_ptr, wT_proj, b_proj, out, nullptr, 1);
}

// round 8
// speedup vs baseline: 1.0401x; 1.0401x over previous
#include <cuda_runtime.h>
#include <cstdint>

#define BATCH 4
#define SEQ   1024
#define NXD   1024
#define NHEAD 16
#define HDIM  64
#define GK    1024

// Scratch (allocation-free rule: __device__ globals)
__device__ float g_q[(size_t)BATCH * NHEAD * SEQ * HDIM];   // tf32-rounded, pre-scaled
__device__ float g_k[(size_t)BATCH * NHEAD * SEQ * HDIM];   // tf32-rounded copy of K
__device__ float g_v[(size_t)BATCH * NHEAD * SEQ * HDIM];   // tf32-rounded copy of V
__device__ float g_a[(size_t)BATCH * SEQ * NXD];            // tf32-rounded
__device__ float g_x[(size_t)BATCH * SEQ * NXD];            // tf32-rounded copy of x
__device__ float g_wT_attn[(size_t)3 * NXD * NXD];          // tf32-rounded [3072,1024]
__device__ float g_wT_proj[(size_t)NXD * NXD];              // tf32-rounded [1024,1024]

__device__ __forceinline__ uint32_t smem_u32(const void* p) {
    uint32_t a;
    asm("{ .reg .u64 t; cvta.to.shared.u64 t, %1; cvt.u32.u64 %0, t; }"
        : "=r"(a) : "l"(p));
    return a;
}
__device__ __forceinline__ uint32_t cvt_tf32(float f) {
    uint32_t r;
    asm("cvt.rna.tf32.f32 %0, %1;" : "=r"(r) : "f"(f));
    return r;
}
__device__ __forceinline__ float rnd_tf32(float f) {
    return __uint_as_float(cvt_tf32(f));
}
__device__ __forceinline__ void cp16(uint32_t dst, const void* src) {
    asm volatile("cp.async.cg.shared.global [%0], [%1], 16;"
                 :: "r"(dst), "l"(src) : "memory");
}
__device__ __forceinline__ void cp_commit() {
    asm volatile("cp.async.commit_group;" ::: "memory");
}
__device__ __forceinline__ void mma_tf32(float* d,
    uint32_t a0, uint32_t a1, uint32_t a2, uint32_t a3,
    uint32_t b0, uint32_t b1)
{
    asm volatile(
        "mma.sync.aligned.m16n8k8.row.col.f32.tf32.tf32.f32 "
        "{%0,%1,%2,%3}, {%4,%5,%6,%7}, {%8,%9}, {%0,%1,%2,%3};"
        : "+f"(d[0]), "+f"(d[1]), "+f"(d[2]), "+f"(d[3])
        : "r"(a0), "r"(a1), "r"(a2), "r"(a3), "r"(b0), "r"(b1));
}

// ---------------------------------------------------------------------------
__global__ void __launch_bounds__(256) cvt_copy_kernel(
    const float* __restrict__ src, float* __restrict__ dst)
{
    int i = blockIdx.x * 256 + threadIdx.x;
    float4 v = ((const float4*)src)[i];
    v.x = rnd_tf32(v.x); v.y = rnd_tf32(v.y);
    v.z = rnd_tf32(v.z); v.w = rnd_tf32(v.w);
    ((float4*)dst)[i] = v;
}

__global__ void __launch_bounds__(256) transpose_kernel(
    const float* __restrict__ src, float* __restrict__ dst, int R, int C)
{
    __shared__ float tile[32][33];
    int c0 = blockIdx.x * 32, r0 = blockIdx.y * 32;
    int tx = threadIdx.x & 31, ty = threadIdx.x >> 5;
#pragma unroll
    for (int i = 0; i < 32; i += 8)
        tile[ty + i][tx] = src[(size_t)(r0 + ty + i) * C + c0 + tx];
    __syncthreads();
#pragma unroll
    for (int i = 0; i < 32; i += 8)
        dst[(size_t)(c0 + ty + i) * R + r0 + tx] = rnd_tf32(tile[tx][ty + i]);
}

// ---------------------------------------------------------------------------
// tf32 mma.sync GEMM, pre-rounded inputs, 256 threads, warp tile 64x64.
// Block tile 128x256, BK=32, 3-stage cp.async, FRAGMENT DOUBLE BUFFERING.
// ---------------------------------------------------------------------------
#define TLD 36
#define STG (384 * TLD)
#define GEMM_SMEM (3 * STG * 4)         // 165,888 B

#define LOAD_FRAGS(KS, AF, BF)                                            \
    do {                                                                  \
        const int k_ = (KS) * 8;                                          \
        _Pragma("unroll")                                                 \
        for (int mt_ = 0; mt_ < 4; mt_++) {                               \
            const uint32_t* ap = ab + (wm * 64 + mt_ * 16 + qr) * TLD + k_ + qc; \
            (AF)[mt_][0] = ap[0];                                         \
            (AF)[mt_][1] = ap[8 * TLD];                                   \
            (AF)[mt_][2] = ap[4];                                         \
            (AF)[mt_][3] = ap[8 * TLD + 4];                               \
        }                                                                 \
        _Pragma("unroll")                                                 \
        for (int nt_ = 0; nt_ < 8; nt_++) {                               \
            const uint32_t* bp = bb + (wn * 64 + nt_ * 8 + qr) * TLD + k_ + qc; \
            (BF)[nt_][0] = bp[0];                                         \
            (BF)[nt_][1] = bp[4];                                         \
        }                                                                 \
    } while (0)

__global__ void __launch_bounds__(256, 1) gemm_mma_kernel(
    const float* __restrict__ A, const float* __restrict__ BT,
    const float* __restrict__ bias, float* __restrict__ Cout,
    float* __restrict__ present, int mode)
{
    extern __shared__ float sm[];

    const int t = threadIdx.x;
    const int lane = t & 31, w = t >> 5;
    const int wm = w >> 2, wn = w & 3;          // 2 x 4 warp grid, 64x64 each
    const int qr = lane >> 2, qc = lane & 3;
    const int m0 = blockIdx.y * 128;
    const int n0 = blockIdx.x * 256;

    uint32_t sa_[3], sb_[3];
#pragma unroll
    for (int s = 0; s < 3; s++) {
        sa_[s] = smem_u32(sm + s * STG);
        sb_[s] = sa_[s] + 128 * TLD * 4;
    }

    float acc[4][8][4];
#pragma unroll
    for (int mt = 0; mt < 4; mt++)
#pragma unroll
        for (int nt = 0; nt < 8; nt++)
#pragma unroll
            for (int r = 0; r < 4; r++) acc[mt][nt][r] = 0.f;

#pragma unroll
    for (int s = 0; s < 2; s++) {
        const int k0 = s * 32;
#pragma unroll
        for (int i = 0; i < 4; i++) {
            int idx = t + i * 256;
            int row = idx >> 3, ch = idx & 7;
            cp16(sa_[s] + ((uint32_t)row * TLD + ch * 4) * 4,
                 A + (size_t)(m0 + row) * GK + k0 + ch * 4);
        }
#pragma unroll
        for (int i = 0; i < 8; i++) {
            int idx = t + i * 256;
            int row = idx >> 3, ch = idx & 7;
            cp16(sb_[s] + ((uint32_t)row * TLD + ch * 4) * 4,
                 BT + (size_t)(n0 + row) * GK + k0 + ch * 4);
        }
        cp_commit();
    }

    for (int kb = 0; kb < 32; kb++) {
        if (kb < 30)
            asm volatile("cp.async.wait_group 1;" ::: "memory");
        else
            asm volatile("cp.async.wait_group 0;" ::: "memory");
        __syncthreads();

        if (kb + 2 < 32) {
            const int s = (kb + 2) % 3;
            const int k0 = (kb + 2) * 32;
#pragma unroll
            for (int i = 0; i < 4; i++) {
                int idx = t + i * 256;
                int row = idx >> 3, ch = idx & 7;
                cp16(sa_[s] + ((uint32_t)row * TLD + ch * 4) * 4,
                     A + (size_t)(m0 + row) * GK + k0 + ch * 4);
            }
#pragma unroll
            for (int i = 0; i < 8; i++) {
                int idx = t + i * 512;
                int row = idx >> 3, ch = idx & 7;
                if (i < 8) {
                    int idx2 = t + i * 256;
                    row = idx2 >> 3; ch = idx2 & 7;
                    cp16(sb_[s] + ((uint32_t)row * TLD + ch * 4) * 4,
                         BT + (size_t)(n0 + row) * GK + k0 + ch * 4);
                }
            }
            cp_commit();
        }

        const uint32_t* ab = (const uint32_t*)(sm + (kb % 3) * STG);
        const uint32_t* bb = ab + 128 * TLD;

        uint32_t af[2][4][4], bf[2][8][2];
        LOAD_FRAGS(0, af[0], bf[0]);
#pragma unroll
        for (int ks = 0; ks < 4; ks++) {
            const int cur = ks & 1, nxt = cur ^ 1;
            if (ks < 3) LOAD_FRAGS(ks + 1, af[nxt], bf[nxt]);
#pragma unroll
            for (int mt = 0; mt < 4; mt++)
#pragma unroll
                for (int nt = 0; nt < 8; nt++)
                    mma_tf32(acc[mt][nt],
                             af[cur][mt][0], af[cur][mt][1], af[cur][mt][2], af[cur][mt][3],
                             bf[cur][nt][0], bf[cur][nt][1]);
        }
    }

#pragma unroll
    for (int mt = 0; mt < 4; mt++) {
#pragma unroll
        for (int nt = 0; nt < 8; nt++) {
            int row = m0 + wm * 64 + mt * 16 + qr;
            int col = n0 + wn * 64 + nt * 8 + qc * 2;
            float bv0 = bias[col], bv1 = bias[col + 1];
            float v00 = acc[mt][nt][0] + bv0, v01 = acc[mt][nt][1] + bv1;
            float v10 = acc[mt][nt][2] + bv0, v11 = acc[mt][nt][3] + bv1;
            if (mode == 1) {
                *(float2*)(Cout + (size_t)row * NXD + col) = make_float2(v00, v01);
                *(float2*)(Cout + (size_t)(row + 8) * NXD + col) = make_float2(v10, v11);
            } else {
                int sec = col >> 10;
                int hn = col & 1023;
                int h = hn >> 6, d = hn & 63;
                int b0_ = row >> 10, s0_ = row & 1023;
                size_t i0 = (((size_t)b0_ * NHEAD + h) * SEQ + s0_) * HDIM + d;
                int b1_ = (row + 8) >> 10, s1_ = (row + 8) & 1023;
                size_t i1 = (((size_t)b1_ * NHEAD + h) * SEQ + s1_) * HDIM + d;
                if (sec == 0) {          // q: scale + round, scratch only
                    *(float2*)(g_q + i0) =
                        make_float2(rnd_tf32(v00 * 0.125f), rnd_tf32(v01 * 0.125f));
                    *(float2*)(g_q + i1) =
                        make_float2(rnd_tf32(v10 * 0.125f), rnd_tf32(v11 * 0.125f));
                } else if (sec == 1) {   // k: exact to present + rounded scratch
                    *(float2*)(present + i0) = make_float2(v00, v01);
                    *(float2*)(present + i1) = make_float2(v10, v11);
                    *(float2*)(g_k + i0) = make_float2(rnd_tf32(v00), rnd_tf32(v01));
                    *(float2*)(g_k + i1) = make_float2(rnd_tf32(v10), rnd_tf32(v11));
                } else {                 // v
                    float* pv = present + (size_t)BATCH * NHEAD * SEQ * HDIM;
                    *(float2*)(pv + i0) = make_float2(v00, v01);
                    *(float2*)(pv + i1) = make_float2(v10, v11);
                    *(float2*)(g_v + i0) = make_float2(rnd_tf32(v00), rnd_tf32(v01));
                    *(float2*)(g_v + i1) = make_float2(rnd_tf32(v10), rnd_tf32(v11));
                }
            }
        }
    }
}

// ---------------------------------------------------------------------------
// Attention: tf32 mma.sync, FA2 fragment softmax. Zero cvt in mainloop
// (q/k/v pre-rounded). Q frags hoisted; K/V frag double buffering.
// ---------------------------------------------------------------------------
#define ALD 68
#define ATTN_SMEM (512 * ALD * 4)   // 139,264 B

__global__ void __launch_bounds__(256, 1) attn_mma_kernel()
{
    extern __shared__ float sma[];
    float* Qs = sma;                          // [128][ALD]
    float* Ksb = Qs + 128 * ALD;              // 2 x [64][ALD] (kpos, d)
    float* Vsb = Ksb + 2 * 64 * ALD;          // 2 x [64][ALD] (kpos, d)
    uint32_t* Ps = (uint32_t*)(Vsb + 2 * 64 * ALD);  // [128][ALD]

    const int t = threadIdx.x;
    const int lane = t & 31, w = t >> 5;
    const int qr = lane >> 2, qc = lane & 3;
    const int q0 = blockIdx.x * 128;
    const int h = blockIdx.y;
    const int b = blockIdx.z;

    const float* qptr = g_q + ((size_t)b * NHEAD + h) * SEQ * HDIM;
    const float* kptr = g_k + ((size_t)b * NHEAD + h) * SEQ * HDIM;
    const float* vptr = g_v + ((size_t)b * NHEAD + h) * SEQ * HDIM;

    const uint32_t qs_a = smem_u32(Qs);
    const uint32_t ks_a[2] = { smem_u32(Ksb), smem_u32(Ksb + 64 * ALD) };
    const uint32_t vs_a[2] = { smem_u32(Vsb), smem_u32(Vsb + 64 * ALD) };

#pragma unroll
    for (int i = 0; i < 8; i++) {
        int c = t + i * 256;
        int row = c >> 4, ch = c & 15;
        cp16(qs_a + ((uint32_t)row * ALD + ch * 4) * 4,
             qptr + (size_t)(q0 + row) * HDIM + ch * 4);
    }
#pragma unroll
    for (int i = 0; i < 4; i++) {
        int c = t + i * 256;
        int row = c >> 4, ch = c & 15;
        uint32_t off = ((uint32_t)row * ALD + ch * 4) * 4;
        cp16(ks_a[0] + off, kptr + (size_t)row * HDIM + ch * 4);
        cp16(vs_a[0] + off, vptr + (size_t)row * HDIM + ch * 4);
    }
    cp_commit();

    float oacc[8][4];
#pragma unroll
    for (int nt = 0; nt < 8; nt++)
#pragma unroll
        for (int r = 0; r < 4; r++) oacc[nt][r] = 0.f;
    float m0 = -1e30f, m1 = -1e30f, l0 = 0.f, l1 = 0.f;

    const int wrow = w * 16;
    const int qg0 = q0 + wrow + qr;
    const int qg1 = qg0 + 8;
    const int qmax = q0 + wrow + 15;
    const int nj = blockIdx.x * 2 + 2;

    // first tile ready; hoist Q fragments (loop-invariant)
    asm volatile("cp.async.wait_group 0;" ::: "memory");
    __syncthreads();
    uint32_t qf[8][4];
    {
        const uint32_t* Qu = (const uint32_t*)Qs;
#pragma unroll
        for (int ks = 0; ks < 8; ks++) {
            const int k = ks * 8;
            qf[ks][0] = Qu[(wrow + qr) * ALD + k + qc];
            qf[ks][1] = Qu[(wrow + qr + 8) * ALD + k + qc];
            qf[ks][2] = Qu[(wrow + qr) * ALD + k + qc + 4];
            qf[ks][3] = Qu[(wrow + qr + 8) * ALD + k + qc + 4];
        }
    }

    for (int jt = 0; jt < nj; jt++) {
        const int j0 = jt * 64;
        if (jt > 0) {
            asm volatile("cp.async.wait_group 0;" ::: "memory");
            __syncthreads();
        }
        if (jt + 1 < nj) {
            const int buf = (jt + 1) & 1;
            const int jr = (jt + 1) * 64;
#pragma unroll
            for (int i = 0; i < 4; i++) {
                int c = t + i * 256;
                int row = c >> 4, ch = c & 15;
                uint32_t off = ((uint32_t)row * ALD + ch * 4) * 4;
                cp16(ks_a[buf] + off, kptr + (size_t)(jr + row) * HDIM + ch * 4);
                cp16(vs_a[buf] + off, vptr + (size_t)(jr + row) * HDIM + ch * 4);
            }
            cp_commit();
        }
        if (j0 > qmax) continue;

        const uint32_t* Ku = (const uint32_t*)(Ksb + (jt & 1) * 64 * ALD);
        const uint32_t* Vu = (const uint32_t*)(Vsb + (jt & 1) * 64 * ALD);

        // ---- S = Q @ K^T (K-frag double buffer) ----
        float sacc[8][4];
#pragma unroll
        for (int nt = 0; nt < 8; nt++)
#pragma unroll
            for (int r = 0; r < 4; r++) sacc[nt][r] = 0.f;

        uint32_t kf[2][8][2];
#pragma unroll
        for (int nt = 0; nt < 8; nt++) {
            kf[0][nt][0] = Ku[(nt * 8 + qr) * ALD + qc];
            kf[0][nt][1] = Ku[(nt * 8 + qr) * ALD + qc + 4];
        }
#pragma unroll
        for (int ks = 0; ks < 8; ks++) {
            const int cur = ks & 1, nxt = cur ^ 1;
            if (ks < 7) {
                const int k = (ks + 1) * 8;
#pragma unroll
                for (int nt = 0; nt < 8; nt++) {
                    kf[nxt][nt][0] = Ku[(nt * 8 + qr) * ALD + k + qc];
                    kf[nxt][nt][1] = Ku[(nt * 8 + qr) * ALD + k + qc + 4];
                }
            }
#pragma unroll
            for (int nt = 0; nt < 8; nt++)
                mma_tf32(sacc[nt], qf[ks][0], qf[ks][1], qf[ks][2], qf[ks][3],
                         kf[cur][nt][0], kf[cur][nt][1]);
        }

        // ---- causal mask + row max ----
        float rx0 = -1e30f, rx1 = -1e30f;
#pragma unroll
        for (int nt = 0; nt < 8; nt++) {
            int kg = j0 + nt * 8 + qc * 2;
            if (kg > qg0)     sacc[nt][0] = -1e30f;
            if (kg + 1 > qg0) sacc[nt][1] = -1e30f;
            if (kg > qg1)     sacc[nt][2] = -1e30f;
            if (kg + 1 > qg1) sacc[nt][3] = -1e30f;
            rx0 = fmaxf(rx0, fmaxf(sacc[nt][0], sacc[nt][1]));
            rx1 = fmaxf(rx1, fmaxf(sacc[nt][2], sacc[nt][3]));
        }
        rx0 = fmaxf(rx0, __shfl_xor_sync(0xffffffffu, rx0, 1));
        rx0 = fmaxf(rx0, __shfl_xor_sync(0xffffffffu, rx0, 2));
        rx1 = fmaxf(rx1, __shfl_xor_sync(0xffffffffu, rx1, 1));
        rx1 = fmaxf(rx1, __shfl_xor_sync(0xffffffffu, rx1, 2));

        float nm0 = fmaxf(m0, rx0), nm1 = fmaxf(m1, rx1);
        float cr0 = __expf(m0 - nm0), cr1 = __expf(m1 - nm1);

        // ---- exp, row sum, stage P (tf32) ----
        float rs0 = 0.f, rs1 = 0.f;
#pragma unroll
        for (int nt = 0; nt < 8; nt++) {
            float p00 = __expf(sacc[nt][0] - nm0);
            float p01 = __expf(sacc[nt][1] - nm0);
            float p10 = __expf(sacc[nt][2] - nm1);
            float p11 = __expf(sacc[nt][3] - nm1);
            rs0 += p00 + p01;
            rs1 += p10 + p11;
            uint32_t col = nt * 8 + qc * 2;
            *(uint2*)&Ps[(wrow + qr) * ALD + col]     = make_uint2(cvt_tf32(p00), cvt_tf32(p01));
            *(uint2*)&Ps[(wrow + qr + 8) * ALD + col] = make_uint2(cvt_tf32(p10), cvt_tf32(p11));
        }
        rs0 += __shfl_xor_sync(0xffffffffu, rs0, 1);
        rs0 += __shfl_xor_sync(0xffffffffu, rs0, 2);
        rs1 += __shfl_xor_sync(0xffffffffu, rs1, 1);
        rs1 += __shfl_xor_sync(0xffffffffu, rs1, 2);

        l0 = l0 * cr0 + rs0;  m0 = nm0;
        l1 = l1 * cr1 + rs1;  m1 = nm1;
#pragma unroll
        for (int nt = 0; nt < 8; nt++) {
            oacc[nt][0] *= cr0;  oacc[nt][1] *= cr0;
            oacc[nt][2] *= cr1;  oacc[nt][3] *= cr1;
        }
        __syncwarp();

        // ---- O += P @ V (V-frag double buffer) ----
        uint32_t vf[2][8][2];
#pragma unroll
        for (int nt = 0; nt < 8; nt++) {
            vf[0][nt][0] = Vu[(qc) * ALD + nt * 8 + qr];
            vf[0][nt][1] = Vu[(qc + 4) * ALD + nt * 8 + qr];
        }
#pragma unroll
        for (int ks = 0; ks < 8; ks++) {
            const int cur = ks & 1, nxt = cur ^ 1;
            const int k = ks * 8;
            if (ks < 7) {
                const int k2 = (ks + 1) * 8;
#pragma unroll
                for (int nt = 0; nt < 8; nt++) {
                    vf[nxt][nt][0] = Vu[(k2 + qc) * ALD + nt * 8 + qr];
                    vf[nxt][nt][1] = Vu[(k2 + qc + 4) * ALD + nt * 8 + qr];
                }
            }
            uint32_t a0 = Ps[(wrow + qr) * ALD + k + qc];
            uint32_t a1 = Ps[(wrow + qr + 8) * ALD + k + qc];
            uint32_t a2 = Ps[(wrow + qr) * ALD + k + qc + 4];
            uint32_t a3 = Ps[(wrow + qr + 8) * ALD + k + qc + 4];
#pragma unroll
            for (int nt = 0; nt < 8; nt++)
                mma_tf32(oacc[nt], a0, a1, a2, a3, vf[cur][nt][0], vf[cur][nt][1]);
        }
        __syncwarp();
    }

    // ---- epilogue ----
    __syncthreads();
    float* Pf = (float*)Ps;
    float inv0 = 1.f / l0, inv1 = 1.f / l1;
#pragma unroll
    for (int nt = 0; nt < 8; nt++) {
        uint32_t col = nt * 8 + qc * 2;
        *(float2*)&Pf[(wrow + qr) * ALD + col] =
            make_float2(oacc[nt][0] * inv0, oacc[nt][1] * inv0);
        *(float2*)&Pf[(wrow + qr + 8) * ALD + col] =
            make_float2(oacc[nt][2] * inv1, oacc[nt][3] * inv1);
    }
    __syncthreads();
    for (int idx = t; idx < 128 * 16; idx += 256) {
        int row = idx >> 4, ch = idx & 15;
        float4 v = *(float4*)&Pf[row * ALD + ch * 4];
        v.x = rnd_tf32(v.x); v.y = rnd_tf32(v.y);
        v.z = rnd_tf32(v.z); v.w = rnd_tf32(v.w);
        *(float4*)(g_a + ((size_t)b * SEQ + q0 + row) * NXD + h * HDIM + ch * 4) = v;
    }
}

// ---------------------------------------------------------------------------
extern "C" void kernel_launch(void* const* d_in, const int* in_sizes, int n_in,
                              void* d_out, int out_size)
{
    const float* x      = (const float*)d_in[0];
    const float* w_attn = (const float*)d_in[1];
    const float* b_attn = (const float*)d_in[2];
    const float* w_proj = (const float*)d_in[3];
    const float* b_proj = (const float*)d_in[4];

    float* out = (float*)d_out;
    float* present = out + (size_t)BATCH * SEQ * NXD;  // (2,B,NH,S,HD)

    cudaFuncSetAttribute(gemm_mma_kernel,
                         cudaFuncAttributeMaxDynamicSharedMemorySize, GEMM_SMEM);
    cudaFuncSetAttribute(attn_mma_kernel,
                         cudaFuncAttributeMaxDynamicSharedMemorySize, ATTN_SMEM);

    float* wT_attn;  cudaGetSymbolAddress((void**)&wT_attn, g_wT_attn);
    float* wT_proj;  cudaGetSymbolAddress((void**)&wT_proj, g_wT_proj);
    float* a_ptr;    cudaGetSymbolAddress((void**)&a_ptr, g_a);
    float* x_ptr;    cudaGetSymbolAddress((void**)&x_ptr, g_x);

    cvt_copy_kernel<<<(BATCH * SEQ * NXD / 4) / 256, 256>>>(x, x_ptr);
    transpose_kernel<<<dim3(3 * NXD / 32, NXD / 32), 256>>>(w_attn, wT_attn, NXD, 3 * NXD);
    transpose_kernel<<<dim3(NXD / 32, NXD / 32), 256>>>(w_proj, wT_proj, NXD, NXD);

    gemm_mma_kernel<<<dim3(3 * NXD / 256, BATCH * SEQ / 128), 256, GEMM_SMEM>>>(
        x_ptr, wT_attn, b_attn, nullptr, present, 0);

    attn_mma_kernel<<<dim3(SEQ / 128, NHEAD, BATCH), 256, ATTN_SMEM>>>();

    gemm_mma_kernel<<<dim3(NXD / 256, BATCH * SEQ / 128), 256, GEMM_SMEM>>>(
        a_ptr, wT_proj, b_proj, out, nullptr, 1);
}

// round 9
// speedup vs baseline: 1.8928x; 1.8198x over previous
#include <cuda_runtime.h>
#include <cuda_fp16.h>
#include <cstdint>

#define BATCH 4
#define SEQ   1024
#define NXD   1024
#define NHEAD 16
#define HDIM  64
#define GK    1024

// Scratch (allocation-free rule: __device__ globals) — fp16 internals
__device__ __half g_q[(size_t)BATCH * NHEAD * SEQ * HDIM];   // pre-scaled by 1/8
__device__ __half g_k[(size_t)BATCH * NHEAD * SEQ * HDIM];
__device__ __half g_v[(size_t)BATCH * NHEAD * SEQ * HDIM];   // [b,h,s,d]
__device__ __half g_vT[(size_t)BATCH * NHEAD * SEQ * HDIM];  // [b,h,d,s]
__device__ __half g_a[(size_t)BATCH * SEQ * NXD];
__device__ __half g_x[(size_t)BATCH * SEQ * NXD];
__device__ __half g_wT_attn[(size_t)3 * NXD * NXD];          // [3072,1024]
__device__ __half g_wT_proj[(size_t)NXD * NXD];              // [1024,1024]

__device__ __forceinline__ uint32_t smem_u32(const void* p) {
    uint32_t a;
    asm("{ .reg .u64 t; cvta.to.shared.u64 t, %1; cvt.u32.u64 %0, t; }"
        : "=r"(a) : "l"(p));
    return a;
}
__device__ __forceinline__ uint32_t packh2(float a, float b) {
    __half2 h = __floats2half2_rn(a, b);
    return *(uint32_t*)&h;
}
__device__ __forceinline__ void cp16(uint32_t dst, const void* src) {
    asm volatile("cp.async.cg.shared.global [%0], [%1], 16;"
                 :: "r"(dst), "l"(src) : "memory");
}
__device__ __forceinline__ void cp_commit() {
    asm volatile("cp.async.commit_group;" ::: "memory");
}
__device__ __forceinline__ void mma_f16(float* d,
    uint32_t a0, uint32_t a1, uint32_t a2, uint32_t a3,
    uint32_t b0, uint32_t b1)
{
    asm volatile(
        "mma.sync.aligned.m16n8k16.row.col.f32.f16.f16.f32 "
        "{%0,%1,%2,%3}, {%4,%5,%6,%7}, {%8,%9}, {%0,%1,%2,%3};"
        : "+f"(d[0]), "+f"(d[1]), "+f"(d[2]), "+f"(d[3])
        : "r"(a0), "r"(a1), "r"(a2), "r"(a3), "r"(b0), "r"(b1));
}

// ---------------------------------------------------------------------------
// prep: fp32 -> fp16 copy of x
// ---------------------------------------------------------------------------
__global__ void __launch_bounds__(256) cvt_copy_kernel(
    const float* __restrict__ src, __half* __restrict__ dst)
{
    int i = blockIdx.x * 256 + threadIdx.x;
    float4 v = ((const float4*)src)[i];
    uint2 o;
    o.x = packh2(v.x, v.y);
    o.y = packh2(v.z, v.w);
    ((uint2*)dst)[i] = o;
}

// weight transpose fp32 -> fp16: dst[C][R] = h(src[R][C])
__global__ void __launch_bounds__(256) transpose_kernel(
    const float* __restrict__ src, __half* __restrict__ dst, int R, int C)
{
    __shared__ float tile[32][33];
    int c0 = blockIdx.x * 32, r0 = blockIdx.y * 32;
    int tx = threadIdx.x & 31, ty = threadIdx.x >> 5;
#pragma unroll
    for (int i = 0; i < 32; i += 8)
        tile[ty + i][tx] = src[(size_t)(r0 + ty + i) * C + c0 + tx];
    __syncthreads();
#pragma unroll
    for (int i = 0; i < 32; i += 8)
        dst[(size_t)(c0 + ty + i) * R + r0 + tx] = __float2half(tile[tx][ty + i]);
}

// V transpose fp16: g_v [b,h,s,d] -> g_vT [b,h,d,s]
__global__ void __launch_bounds__(256) vtrans_kernel()
{
    __shared__ __half tile[32][33];
    int bh = blockIdx.z;
    int s0 = blockIdx.x * 32, d0 = blockIdx.y * 32;
    const __half* src = g_v + (size_t)bh * SEQ * HDIM;
    __half* dst = g_vT + (size_t)bh * SEQ * HDIM;
    int tx = threadIdx.x & 31, ty = threadIdx.x >> 5;
#pragma unroll
    for (int i = 0; i < 32; i += 8)
        tile[ty + i][tx] = src[(size_t)(s0 + ty + i) * HDIM + d0 + tx];
    __syncthreads();
#pragma unroll
    for (int i = 0; i < 32; i += 8)
        dst[(size_t)(d0 + ty + i) * SEQ + s0 + tx] = tile[tx][ty + i];
}

// ---------------------------------------------------------------------------
// fp16 mma.sync GEMM (fp32 accum). Block 128x256, BK=64, 8 warps (64x64),
// 3-stage cp.async. Smem rows = 36 u32 (= 72 halves, conflict-free).
// C[m][n] = sum_k A[m][k] * BT[n][k] + bias[n]
// ---------------------------------------------------------------------------
#define TLD2 36                          // u32 per smem row
#define STG32 (384 * TLD2)               // u32 per stage (A 128 + B 256 rows)
#define GEMM_SMEM (3 * STG32 * 4)        // 165,888 B

__global__ void __launch_bounds__(256, 1) gemm_mma_kernel(
    const __half* __restrict__ A, const __half* __restrict__ BT,
    const float* __restrict__ bias, float* __restrict__ Cout,
    float* __restrict__ present, int mode)
{
    extern __shared__ uint32_t sm32[];

    const int t = threadIdx.x;
    const int lane = t & 31, w = t >> 5;
    const int wm = w >> 2, wn = w & 3;          // 2 x 4 warps, 64x64 each
    const int qr = lane >> 2, qc = lane & 3;
    const int m0 = blockIdx.y * 128;
    const int n0 = blockIdx.x * 256;

    uint32_t sa_[3], sb_[3];
#pragma unroll
    for (int s = 0; s < 3; s++) {
        sa_[s] = smem_u32(sm32 + s * STG32);
        sb_[s] = sa_[s] + 128 * TLD2 * 4;
    }

    float acc[4][8][4];
#pragma unroll
    for (int mt = 0; mt < 4; mt++)
#pragma unroll
        for (int nt = 0; nt < 8; nt++)
#pragma unroll
            for (int r = 0; r < 4; r++) acc[mt][nt][r] = 0.f;

    // per stage: A 1024 chunks (128 rows x 8), B 2048 chunks (256 x 8); 16B=8 halves
#pragma unroll
    for (int s = 0; s < 2; s++) {
        const int k0 = s * 64;
#pragma unroll
        for (int i = 0; i < 4; i++) {
            int idx = t + i * 256;
            int row = idx >> 3, ch = idx & 7;
            cp16(sa_[s] + ((uint32_t)row * TLD2 + ch * 4) * 4,
                 A + (size_t)(m0 + row) * GK + k0 + ch * 8);
        }
#pragma unroll
        for (int i = 0; i < 8; i++) {
            int idx = t + i * 256;
            int row = idx >> 3, ch = idx & 7;
            cp16(sb_[s] + ((uint32_t)row * TLD2 + ch * 4) * 4,
                 BT + (size_t)(n0 + row) * GK + k0 + ch * 8);
        }
        cp_commit();
    }

    for (int kb = 0; kb < 16; kb++) {
        if (kb < 14)
            asm volatile("cp.async.wait_group 1;" ::: "memory");
        else
            asm volatile("cp.async.wait_group 0;" ::: "memory");
        __syncthreads();

        if (kb + 2 < 16) {
            const int s = (kb + 2) % 3;
            const int k0 = (kb + 2) * 64;
#pragma unroll
            for (int i = 0; i < 4; i++) {
                int idx = t + i * 256;
                int row = idx >> 3, ch = idx & 7;
                cp16(sa_[s] + ((uint32_t)row * TLD2 + ch * 4) * 4,
                     A + (size_t)(m0 + row) * GK + k0 + ch * 8);
            }
#pragma unroll
            for (int i = 0; i < 8; i++) {
                int idx = t + i * 256;
                int row = idx >> 3, ch = idx & 7;
                cp16(sb_[s] + ((uint32_t)row * TLD2 + ch * 4) * 4,
                     BT + (size_t)(n0 + row) * GK + k0 + ch * 8);
            }
            cp_commit();
        }

        const uint32_t* ab = sm32 + (kb % 3) * STG32;
        const uint32_t* bb = ab + 128 * TLD2;
#pragma unroll
        for (int ks = 0; ks < 4; ks++) {        // 4 k16 steps per BK=64
            const int k2 = ks * 8;              // h2 offset
            uint32_t af[4][4], bf[8][2];
#pragma unroll
            for (int mt = 0; mt < 4; mt++) {
                const uint32_t* ap = ab + (wm * 64 + mt * 16 + qr) * TLD2 + k2 + qc;
                af[mt][0] = ap[0];
                af[mt][1] = ap[8 * TLD2];
                af[mt][2] = ap[4];
                af[mt][3] = ap[8 * TLD2 + 4];
            }
#pragma unroll
            for (int nt = 0; nt < 8; nt++) {
                const uint32_t* bp = bb + (wn * 64 + nt * 8 + qr) * TLD2 + k2 + qc;
                bf[nt][0] = bp[0];
                bf[nt][1] = bp[4];
            }
#pragma unroll
            for (int mt = 0; mt < 4; mt++)
#pragma unroll
                for (int nt = 0; nt < 8; nt++)
                    mma_f16(acc[mt][nt], af[mt][0], af[mt][1], af[mt][2], af[mt][3],
                            bf[nt][0], bf[nt][1]);
        }
    }

#pragma unroll
    for (int mt = 0; mt < 4; mt++) {
#pragma unroll
        for (int nt = 0; nt < 8; nt++) {
            int row = m0 + wm * 64 + mt * 16 + qr;
            int col = n0 + wn * 64 + nt * 8 + qc * 2;
            float bv0 = bias[col], bv1 = bias[col + 1];
            float v00 = acc[mt][nt][0] + bv0, v01 = acc[mt][nt][1] + bv1;
            float v10 = acc[mt][nt][2] + bv0, v11 = acc[mt][nt][3] + bv1;
            if (mode == 1) {
                *(float2*)(Cout + (size_t)row * NXD + col) = make_float2(v00, v01);
                *(float2*)(Cout + (size_t)(row + 8) * NXD + col) = make_float2(v10, v11);
            } else {
                int sec = col >> 10;
                int hn = col & 1023;
                int h = hn >> 6, d = hn & 63;
                int b0_ = row >> 10, s0_ = row & 1023;
                size_t i0 = (((size_t)b0_ * NHEAD + h) * SEQ + s0_) * HDIM + d;
                int b1_ = (row + 8) >> 10, s1_ = (row + 8) & 1023;
                size_t i1 = (((size_t)b1_ * NHEAD + h) * SEQ + s1_) * HDIM + d;
                if (sec == 0) {          // q -> scratch (scaled)
                    *(uint32_t*)(g_q + i0) = packh2(v00 * 0.125f, v01 * 0.125f);
                    *(uint32_t*)(g_q + i1) = packh2(v10 * 0.125f, v11 * 0.125f);
                } else if (sec == 1) {   // k -> present exact + half scratch
                    *(float2*)(present + i0) = make_float2(v00, v01);
                    *(float2*)(present + i1) = make_float2(v10, v11);
                    *(uint32_t*)(g_k + i0) = packh2(v00, v01);
                    *(uint32_t*)(g_k + i1) = packh2(v10, v11);
                } else {                 // v
                    float* pv = present + (size_t)BATCH * NHEAD * SEQ * HDIM;
                    *(float2*)(pv + i0) = make_float2(v00, v01);
                    *(float2*)(pv + i1) = make_float2(v10, v11);
                    *(uint32_t*)(g_v + i0) = packh2(v00, v01);
                    *(uint32_t*)(g_v + i1) = packh2(v10, v11);
                }
            }
        }
    }
}

// ---------------------------------------------------------------------------
// Attention: fp16 mma.sync (fp32 softmax/acc). P stays in registers
// (C-layout == A-layout when packed half2). Smem 55KB -> 2 CTAs/SM.
// ---------------------------------------------------------------------------
#define ATTN_SMEM ((128 * TLD2 + 2 * 64 * TLD2 + 2 * 64 * TLD2) * 4)  // 55,296 B

__global__ void __launch_bounds__(256, 2) attn_mma_kernel()
{
    extern __shared__ uint32_t sma32[];
    uint32_t* Qs = sma32;                        // [128][36] (q, d) h2
    uint32_t* Ksb = Qs + 128 * TLD2;             // 2 x [64][36] (kpos, d) h2
    uint32_t* Vtb = Ksb + 2 * 64 * TLD2;         // 2 x [64][36] (d, kpos) h2

    const int t = threadIdx.x;
    const int lane = t & 31, w = t >> 5;
    const int qr = lane >> 2, qc = lane & 3;
    const int q0 = blockIdx.x * 128;
    const int h = blockIdx.y;
    const int b = blockIdx.z;

    const __half* qptr = g_q + ((size_t)b * NHEAD + h) * SEQ * HDIM;
    const __half* kptr = g_k + ((size_t)b * NHEAD + h) * SEQ * HDIM;
    const __half* vtp  = g_vT + ((size_t)b * NHEAD + h) * SEQ * HDIM;

    const uint32_t qs_a = smem_u32(Qs);
    const uint32_t ks_a[2] = { smem_u32(Ksb), smem_u32(Ksb + 64 * TLD2) };
    const uint32_t vs_a[2] = { smem_u32(Vtb), smem_u32(Vtb + 64 * TLD2) };

    // prefetch Q (128x64) + K,Vt tile 0 (64x64 each); 16B = 8 halves
#pragma unroll
    for (int i = 0; i < 4; i++) {
        int c = t + i * 256;
        int row = c >> 3, ch = c & 7;
        cp16(qs_a + ((uint32_t)row * TLD2 + ch * 4) * 4,
             qptr + (size_t)(q0 + row) * HDIM + ch * 8);
    }
#pragma unroll
    for (int i = 0; i < 2; i++) {
        int c = t + i * 256;
        int row = c >> 3, ch = c & 7;
        uint32_t off = ((uint32_t)row * TLD2 + ch * 4) * 4;
        cp16(ks_a[0] + off, kptr + (size_t)row * HDIM + ch * 8);
        cp16(vs_a[0] + off, vtp + (size_t)row * SEQ + ch * 8);
    }
    cp_commit();

    float oacc[8][4];
#pragma unroll
    for (int nt = 0; nt < 8; nt++)
#pragma unroll
        for (int r = 0; r < 4; r++) oacc[nt][r] = 0.f;
    float m0 = -1e30f, m1 = -1e30f, l0 = 0.f, l1 = 0.f;

    const int wrow = w * 16;
    const int qg0 = q0 + wrow + qr;
    const int qg1 = qg0 + 8;
    const int qmax = q0 + wrow + 15;
    const int nj = blockIdx.x * 2 + 2;

    asm volatile("cp.async.wait_group 0;" ::: "memory");
    __syncthreads();
    // hoist Q fragments (loop-invariant): 4 k16 steps
    uint32_t qf[4][4];
#pragma unroll
    for (int ks = 0; ks < 4; ks++) {
        const uint32_t* qp = Qs + (wrow + qr) * TLD2 + ks * 8 + qc;
        qf[ks][0] = qp[0];
        qf[ks][1] = qp[8 * TLD2];
        qf[ks][2] = qp[4];
        qf[ks][3] = qp[8 * TLD2 + 4];
    }

    for (int jt = 0; jt < nj; jt++) {
        const int j0 = jt * 64;
        if (jt > 0) {
            asm volatile("cp.async.wait_group 0;" ::: "memory");
            __syncthreads();
        }
        if (jt + 1 < nj) {
            const int buf = (jt + 1) & 1;
            const int jr = (jt + 1) * 64;
#pragma unroll
            for (int i = 0; i < 2; i++) {
                int c = t + i * 256;
                int row = c >> 3, ch = c & 7;
                uint32_t off = ((uint32_t)row * TLD2 + ch * 4) * 4;
                cp16(ks_a[buf] + off, kptr + (size_t)(jr + row) * HDIM + ch * 8);
                cp16(vs_a[buf] + off, vtp + (size_t)row * SEQ + jr + ch * 8);
            }
            cp_commit();
        }
        if (j0 > qmax) continue;

        const uint32_t* Ku = Ksb + (jt & 1) * 64 * TLD2;
        const uint32_t* Vu = Vtb + (jt & 1) * 64 * TLD2;

        // ---- S = Q @ K^T ----
        float sacc[8][4];
#pragma unroll
        for (int nt = 0; nt < 8; nt++)
#pragma unroll
            for (int r = 0; r < 4; r++) sacc[nt][r] = 0.f;

#pragma unroll
        for (int ks = 0; ks < 4; ks++) {
            const int k2 = ks * 8;
#pragma unroll
            for (int nt = 0; nt < 8; nt++) {
                const uint32_t* kp = Ku + (nt * 8 + qr) * TLD2 + k2 + qc;
                mma_f16(sacc[nt], qf[ks][0], qf[ks][1], qf[ks][2], qf[ks][3],
                        kp[0], kp[4]);
            }
        }

        // ---- causal mask + row max ----
        float rx0 = -1e30f, rx1 = -1e30f;
#pragma unroll
        for (int nt = 0; nt < 8; nt++) {
            int kg = j0 + nt * 8 + qc * 2;
            if (kg > qg0)     sacc[nt][0] = -1e30f;
            if (kg + 1 > qg0) sacc[nt][1] = -1e30f;
            if (kg > qg1)     sacc[nt][2] = -1e30f;
            if (kg + 1 > qg1) sacc[nt][3] = -1e30f;
            rx0 = fmaxf(rx0, fmaxf(sacc[nt][0], sacc[nt][1]));
            rx1 = fmaxf(rx1, fmaxf(sacc[nt][2], sacc[nt][3]));
        }
        rx0 = fmaxf(rx0, __shfl_xor_sync(0xffffffffu, rx0, 1));
        rx0 = fmaxf(rx0, __shfl_xor_sync(0xffffffffu, rx0, 2));
        rx1 = fmaxf(rx1, __shfl_xor_sync(0xffffffffu, rx1, 1));
        rx1 = fmaxf(rx1, __shfl_xor_sync(0xffffffffu, rx1, 2));

        float nm0 = fmaxf(m0, rx0), nm1 = fmaxf(m1, rx1);
        float cr0 = __expf(m0 - nm0), cr1 = __expf(m1 - nm1);

        // ---- exp, row sum, pack P to half2 (stays in regs) ----
        float rs0 = 0.f, rs1 = 0.f;
        uint32_t plo[8], phi[8];
#pragma unroll
        for (int nt = 0; nt < 8; nt++) {
            float p00 = __expf(sacc[nt][0] - nm0);
            float p01 = __expf(sacc[nt][1] - nm0);
            float p10 = __expf(sacc[nt][2] - nm1);
            float p11 = __expf(sacc[nt][3] - nm1);
            rs0 += p00 + p01;
            rs1 += p10 + p11;
            plo[nt] = packh2(p00, p01);
            phi[nt] = packh2(p10, p11);
        }
        rs0 += __shfl_xor_sync(0xffffffffu, rs0, 1);
        rs0 += __shfl_xor_sync(0xffffffffu, rs0, 2);
        rs1 += __shfl_xor_sync(0xffffffffu, rs1, 1);
        rs1 += __shfl_xor_sync(0xffffffffu, rs1, 2);

        l0 = l0 * cr0 + rs0;  m0 = nm0;
        l1 = l1 * cr1 + rs1;  m1 = nm1;
#pragma unroll
        for (int nt = 0; nt < 8; nt++) {
            oacc[nt][0] *= cr0;  oacc[nt][1] *= cr0;
            oacc[nt][2] *= cr1;  oacc[nt][3] *= cr1;
        }

        // ---- O += P @ V  (A-frags = packed S-tiles: no smem round trip) ----
#pragma unroll
        for (int j = 0; j < 4; j++) {            // k16 steps over kpos
            uint32_t a0 = plo[2 * j], a1 = phi[2 * j];
            uint32_t a2 = plo[2 * j + 1], a3 = phi[2 * j + 1];
            const int k2 = j * 8;
#pragma unroll
            for (int nt = 0; nt < 8; nt++) {
                const uint32_t* vp = Vu + (nt * 8 + qr) * TLD2 + k2 + qc;
                mma_f16(oacc[nt], a0, a1, a2, a3, vp[0], vp[4]);
            }
        }
    }

    // ---- epilogue: normalize, pack to half2, stage in Qs, coalesced write ----
    __syncthreads();
    float inv0 = 1.f / l0, inv1 = 1.f / l1;
#pragma unroll
    for (int nt = 0; nt < 8; nt++) {
        Qs[(wrow + qr) * TLD2 + nt * 4 + qc] =
            packh2(oacc[nt][0] * inv0, oacc[nt][1] * inv0);
        Qs[(wrow + qr + 8) * TLD2 + nt * 4 + qc] =
            packh2(oacc[nt][2] * inv1, oacc[nt][3] * inv1);
    }
    __syncthreads();
    for (int idx = t; idx < 128 * 32; idx += 256) {
        int row = idx >> 5, c2 = idx & 31;
        *(uint32_t*)(g_a + ((size_t)b * SEQ + q0 + row) * NXD + h * HDIM + c2 * 2) =
            Qs[row * TLD2 + c2];
    }
}

// ---------------------------------------------------------------------------
extern "C" void kernel_launch(void* const* d_in, const int* in_sizes, int n_in,
                              void* d_out, int out_size)
{
    const float* x      = (const float*)d_in[0];
    const float* w_attn = (const float*)d_in[1];
    const float* b_attn = (const float*)d_in[2];
    const float* w_proj = (const float*)d_in[3];
    const float* b_proj = (const float*)d_in[4];

    float* out = (float*)d_out;
    float* present = out + (size_t)BATCH * SEQ * NXD;  // (2,B,NH,S,HD)

    cudaFuncSetAttribute(gemm_mma_kernel,
                         cudaFuncAttributeMaxDynamicSharedMemorySize, GEMM_SMEM);
    cudaFuncSetAttribute(attn_mma_kernel,
                         cudaFuncAttributeMaxDynamicSharedMemorySize, ATTN_SMEM);

    __half* wT_attn;  cudaGetSymbolAddress((void**)&wT_attn, g_wT_attn);
    __half* wT_proj;  cudaGetSymbolAddress((void**)&wT_proj, g_wT_proj);
    __half* a_ptr;    cudaGetSymbolAddress((void**)&a_ptr, g_a);
    __half* x_ptr;    cudaGetSymbolAddress((void**)&x_ptr, g_x);

    cvt_copy_kernel<<<(BATCH * SEQ * NXD / 4) / 256, 256>>>(x, x_ptr);
    transpose_kernel<<<dim3(3 * NXD / 32, NXD / 32), 256>>>(w_attn, wT_attn, NXD, 3 * NXD);
    transpose_kernel<<<dim3(NXD / 32, NXD / 32), 256>>>(w_proj, wT_proj, NXD, NXD);

    gemm_mma_kernel<<<dim3(3 * NXD / 256, BATCH * SEQ / 128), 256, GEMM_SMEM>>>(
        x_ptr, wT_attn, b_attn, nullptr, present, 0);

    vtrans_kernel<<<dim3(SEQ / 32, HDIM / 32, BATCH * NHEAD), 256>>>();

    attn_mma_kernel<<<dim3(SEQ / 128, NHEAD, BATCH), 256, ATTN_SMEM>>>();

    gemm_mma_kernel<<<dim3(NXD / 256, BATCH * SEQ / 128), 256, GEMM_SMEM>>>(
        a_ptr, wT_proj, b_proj, out, nullptr, 1);
}